// round 5
// baseline (speedup 1.0000x reference)
#include <cuda_runtime.h>

// out[i,j] = hA[i] + hB[j] - sum_d m*lg2(m),   m = 0.5*a + 0.5*b
// hA[i] = sum_d 0.5*a*lg2(a) (precomputed). log2 domain => final /ln2 free.
// Inner loop uses packed f32x2 add/fma (Blackwell) to halve fp32 issue count;
// MUFU.LG2 (scalar, 16 lanes/cyc/SM) is the intended pipe floor.

static constexpr int Dc = 512;
static constexpr int TM = 32;
static constexpr int TN = 32;
static constexpr int KB = 32;
static constexpr int LDA = 36;          // floats; 144B rows keep float4 align
static constexpr int NCHUNK = Dc / KB;  // 16

__device__ float g_hA[1024];
__device__ float g_hB[1024];

// ---------------- row half-entropy precompute ---------------------------
__global__ __launch_bounds__(128)
void row_entropy_kernel(const float* __restrict__ A, const float* __restrict__ B,
                        int nA) {
    const int row = blockIdx.x;
    const bool isA = row < nA;
    const int r = isA ? row : row - nA;
    const float* src = isA ? A : B;
    const int t = threadIdx.x;

    float4 v = reinterpret_cast<const float4*>(src + (size_t)r * Dc)[t];
    float s = 0.5f * v.x * __log2f(v.x)
            + 0.5f * v.y * __log2f(v.y)
            + 0.5f * v.z * __log2f(v.z)
            + 0.5f * v.w * __log2f(v.w);

    __shared__ float red[128];
    red[t] = s;
    __syncthreads();
    #pragma unroll
    for (int off = 64; off > 0; off >>= 1) {
        if (t < off) red[t] += red[t + off];
        __syncthreads();
    }
    if (t == 0) {
        if (isA) g_hA[r] = red[0]; else g_hB[r] = red[0];
    }
}

// ---------------- main pairwise kernel ----------------------------------
__global__ __launch_bounds__(128, 8)
void jsd_main(const float* __restrict__ A, const float* __restrict__ B,
              float* __restrict__ out, int M) {
    __shared__ float As[KB][LDA];   // As[d][r] = 0.5 * a[i0+r][k0+d]
    __shared__ float Bs[KB][LDA];

    const int tid = threadIdx.x;
    const int tx = tid & 7;         // 8 col-groups of 4
    const int ty = tid >> 3;        // 16 row-groups of 2
    const int i0 = blockIdx.y * TM;
    const int j0 = blockIdx.x * TN;

    // packed accumulators: acc2[u][vp] holds columns (vp*2, vp*2+1); 0ull == (0.f,0.f)
    unsigned long long acc2[2][2] = {{0ull, 0ull}, {0ull, 0ull}};

    float ra[8], rb[8];
    // preload chunk 0 (coalesced: consecutive tid -> consecutive d)
    #pragma unroll
    for (int e = 0; e < 8; ++e) {
        int idx = e * 128 + tid, r = idx >> 5, d = idx & 31;
        ra[e] = A[(size_t)(i0 + r) * Dc + d];
        rb[e] = B[(size_t)(j0 + r) * Dc + d];
    }

    for (int c = 0; c < NCHUNK; ++c) {
        #pragma unroll
        for (int e = 0; e < 8; ++e) {
            int idx = e * 128 + tid, r = idx >> 5, d = idx & 31;
            As[d][r] = 0.5f * ra[e];
            Bs[d][r] = 0.5f * rb[e];
        }
        __syncthreads();

        if (c + 1 < NCHUNK) {  // prefetch next chunk while computing this one
            const int k0 = (c + 1) * KB;
            #pragma unroll
            for (int e = 0; e < 8; ++e) {
                int idx = e * 128 + tid, r = idx >> 5, d = idx & 31;
                ra[e] = A[(size_t)(i0 + r) * Dc + k0 + d];
                rb[e] = B[(size_t)(j0 + r) * Dc + k0 + d];
            }
        }

        #pragma unroll 8
        for (int d = 0; d < KB; ++d) {
            float2 a2 = *reinterpret_cast<const float2*>(&As[d][ty * 2]);
            // 64-bit LDS -> aligned register pair == ready-made f32x2
            unsigned long long bP[2];
            bP[0] = *reinterpret_cast<const unsigned long long*>(&Bs[d][tx * 4]);
            bP[1] = *reinterpret_cast<const unsigned long long*>(&Bs[d][tx * 4 + 2]);
            unsigned long long aP[2];
            {
                unsigned a0 = __float_as_uint(a2.x), a1 = __float_as_uint(a2.y);
                asm("mov.b64 %0, {%1, %1};" : "=l"(aP[0]) : "r"(a0));
                asm("mov.b64 %0, {%1, %1};" : "=l"(aP[1]) : "r"(a1));
            }
            #pragma unroll
            for (int u = 0; u < 2; ++u)
                #pragma unroll
                for (int vp = 0; vp < 2; ++vp) {
                    unsigned long long m2;
                    asm("add.rn.f32x2 %0, %1, %2;"
                        : "=l"(m2) : "l"(aP[u]), "l"(bP[vp]));
                    unsigned mlo, mhi;
                    asm("mov.b64 {%0, %1}, %2;" : "=r"(mlo), "=r"(mhi) : "l"(m2));
                    float l0 = __log2f(__uint_as_float(mlo));   // MUFU.LG2
                    float l1 = __log2f(__uint_as_float(mhi));   // MUFU.LG2
                    unsigned long long lgp;
                    asm("mov.b64 %0, {%1, %2};"
                        : "=l"(lgp)
                        : "r"(__float_as_uint(l0)), "r"(__float_as_uint(l1)));
                    // acc += m * lg2(m)   (negative-valued; subtracted in epilogue)
                    asm("fma.rn.f32x2 %0, %1, %2, %0;"
                        : "+l"(acc2[u][vp]) : "l"(m2), "l"(lgp));
                }
        }
        __syncthreads();
    }

    // epilogue: out = hA + hB - acc, coalesced float4 stores
    float4 hb = *reinterpret_cast<const float4*>(&g_hB[j0 + tx * 4]);
    float hbv[4] = {hb.x, hb.y, hb.z, hb.w};
    #pragma unroll
    for (int u = 0; u < 2; ++u) {
        float ha = g_hA[i0 + ty * 2 + u];
        float av[4];
        #pragma unroll
        for (int vp = 0; vp < 2; ++vp) {
            unsigned lo, hi;
            asm("mov.b64 {%0, %1}, %2;" : "=r"(lo), "=r"(hi) : "l"(acc2[u][vp]));
            av[vp * 2]     = __uint_as_float(lo);
            av[vp * 2 + 1] = __uint_as_float(hi);
        }
        float4 o = make_float4(ha + hbv[0] - av[0],
                               ha + hbv[1] - av[1],
                               ha + hbv[2] - av[2],
                               ha + hbv[3] - av[3]);
        *reinterpret_cast<float4*>(
            &out[(size_t)(i0 + ty * 2 + u) * M + (j0 + tx * 4)]) = o;
    }
}

extern "C" void kernel_launch(void* const* d_in, const int* in_sizes, int n_in,
                              void* d_out, int out_size) {
    const float* A = (const float*)d_in[0];
    const float* B = (const float*)d_in[1];
    float* out = (float*)d_out;
    const int N = in_sizes[0] / Dc;   // 1024
    const int M = in_sizes[1] / Dc;   // 1024

    row_entropy_kernel<<<N + M, 128>>>(A, B, N);

    dim3 grid(M / TN, N / TM);        // 1024 blocks
    jsd_main<<<grid, 128>>>(A, B, out, M);
}

// round 6
// speedup vs baseline: 1.1066x; 1.1066x over previous
#include <cuda_runtime.h>

// out[i,j] = hA[i] + hB[j] + 1 - 0.5 * sum_d s*lg2(s),  s = a + b  (raw sum!)
// Uses sum_d m*lg2(m) = 0.5*sum_d s*lg2(s) - 1 (rows are normalized), so the
// inner loop needs NO scaling: FADD + MUFU.LG2 + FFMA per element.
// hA[i] = sum_d 0.5*a*lg2(a) precomputed. log2 domain => /ln2 free.

static constexpr int Dc = 512;
static constexpr int TM = 32;
static constexpr int TN = 32;
static constexpr int KB = 32;
static constexpr int LDA = 36;          // floats/row: 144B keeps float4 align
static constexpr int NCHUNK = Dc / KB;  // 16

__device__ float g_hA[1024];
__device__ float g_hB[1024];

// ---------------- row half-entropy precompute ---------------------------
__global__ __launch_bounds__(128)
void row_entropy_kernel(const float* __restrict__ A, const float* __restrict__ B,
                        int nA) {
    const int row = blockIdx.x;
    const bool isA = row < nA;
    const int r = isA ? row : row - nA;
    const float* src = isA ? A : B;
    const int t = threadIdx.x;

    float4 v = reinterpret_cast<const float4*>(src + (size_t)r * Dc)[t];
    float s = 0.5f * v.x * __log2f(v.x)
            + 0.5f * v.y * __log2f(v.y)
            + 0.5f * v.z * __log2f(v.z)
            + 0.5f * v.w * __log2f(v.w);

    __shared__ float red[128];
    red[t] = s;
    __syncthreads();
    #pragma unroll
    for (int off = 64; off > 0; off >>= 1) {
        if (t < off) red[t] += red[t + off];
        __syncthreads();
    }
    if (t == 0) {
        if (isA) g_hA[r] = red[0]; else g_hB[r] = red[0];
    }
}

// ---------------- main pairwise kernel ----------------------------------
// 32x32 tile, 128 threads, 2x4 micro-tile, double-buffered smem,
// register-prefetched GMEM loads, immediate-offset staging addresses.
__global__ __launch_bounds__(128, 8)
void jsd_main(const float* __restrict__ A, const float* __restrict__ B,
              float* __restrict__ out, int M) {
    __shared__ float As[2][KB][LDA];   // As[p][d][r] = a[i0+r][k0+d] (raw)
    __shared__ float Bs[2][KB][LDA];

    const int tid = threadIdx.x;
    const int tx = tid & 7;            // 8 col-groups of 4
    const int ty = tid >> 3;           // 16 row-groups of 2
    const int i0 = blockIdx.y * TM;
    const int j0 = blockIdx.x * TN;

    // staging decomposition: d = tid&31 (fixed), r = e*4 + (tid>>5)
    const int sd = tid & 31;
    const int sw = tid >> 5;

    // per-thread base pointers; all staging addresses are immediates off these
    const float* pA = A + (size_t)(i0 + sw) * Dc + sd;
    const float* pB = B + (size_t)(j0 + sw) * Dc + sd;
    float* stA = &As[0][sd][sw];       // advance by buffer manually
    float* stB = &Bs[0][sd][sw];
    const int BUFSZ = KB * LDA;        // floats between buffer 0 and 1

    float acc[2][4] = {};
    float ra[8], rb[8];

    // ---- preload + stage chunk 0 into buffer 0 ----
    #pragma unroll
    for (int e = 0; e < 8; ++e) {
        ra[e] = pA[e * 4 * Dc];
        rb[e] = pB[e * 4 * Dc];
    }
    #pragma unroll
    for (int e = 0; e < 8; ++e) {
        stA[e * 4] = ra[e];
        stB[e * 4] = rb[e];
    }
    __syncthreads();

    #pragma unroll 1
    for (int c = 0; c < NCHUNK; ++c) {
        const int p = c & 1;

        // prefetch chunk c+1 (LDGs in flight during compute below)
        if (c + 1 < NCHUNK) {
            const float* qA = pA + (c + 1) * KB;
            const float* qB = pB + (c + 1) * KB;
            #pragma unroll
            for (int e = 0; e < 8; ++e) {
                ra[e] = qA[e * 4 * Dc];
                rb[e] = qB[e * 4 * Dc];
            }
        }

        // ---- compute on buffer p: per element FADD + MUFU.LG2 + FFMA ----
        #pragma unroll 8
        for (int d = 0; d < KB; ++d) {
            float2 a2 = *reinterpret_cast<const float2*>(&As[p][d][ty * 2]);
            float4 b4 = *reinterpret_cast<const float4*>(&Bs[p][d][tx * 4]);
            float av[2] = {a2.x, a2.y};
            float bv[4] = {b4.x, b4.y, b4.z, b4.w};
            #pragma unroll
            for (int u = 0; u < 2; ++u)
                #pragma unroll
                for (int v = 0; v < 4; ++v) {
                    float s = av[u] + bv[v];                        // a + b
                    acc[u][v] = __fmaf_rn(s, __log2f(s), acc[u][v]); // += s*lg2(s)
                }
        }

        // ---- stage chunk c+1 into the other buffer ----
        if (c + 1 < NCHUNK) {
            float* wA = stA + (1 - p) * BUFSZ;
            float* wB = stB + (1 - p) * BUFSZ;
            #pragma unroll
            for (int e = 0; e < 8; ++e) {
                wA[e * 4] = ra[e];
                wB[e * 4] = rb[e];
            }
        }
        __syncthreads();
    }

    // epilogue: out = (hA + hB + 1) - 0.5*acc, coalesced float4 stores
    float4 hb = *reinterpret_cast<const float4*>(&g_hB[j0 + tx * 4]);
    float hbv[4] = {hb.x, hb.y, hb.z, hb.w};
    #pragma unroll
    for (int u = 0; u < 2; ++u) {
        float ha1 = g_hA[i0 + ty * 2 + u] + 1.0f;
        float4 o;
        o.x = __fmaf_rn(-0.5f, acc[u][0], ha1 + hbv[0]);
        o.y = __fmaf_rn(-0.5f, acc[u][1], ha1 + hbv[1]);
        o.z = __fmaf_rn(-0.5f, acc[u][2], ha1 + hbv[2]);
        o.w = __fmaf_rn(-0.5f, acc[u][3], ha1 + hbv[3]);
        *reinterpret_cast<float4*>(
            &out[(size_t)(i0 + ty * 2 + u) * M + (j0 + tx * 4)]) = o;
    }
}

extern "C" void kernel_launch(void* const* d_in, const int* in_sizes, int n_in,
                              void* d_out, int out_size) {
    const float* A = (const float*)d_in[0];
    const float* B = (const float*)d_in[1];
    float* out = (float*)d_out;
    const int N = in_sizes[0] / Dc;   // 1024
    const int M = in_sizes[1] / Dc;   // 1024

    row_entropy_kernel<<<N + M, 128>>>(A, B, N);

    dim3 grid(M / TN, N / TM);        // 1024 blocks
    jsd_main<<<grid, 128>>>(A, B, out, M);
}